// round 4
// baseline (speedup 1.0000x reference)
#include <cuda_runtime.h>
#include <math.h>

#define Ldim 4096
#define Edim 512
#define Sdim 1024
#define Hdim 150
#define HP   160       // padded H
#define MAXN 10
#define Ttot 40915     // 10L - 45
#define TP   40960     // padded to 640*64

typedef unsigned long long u64;

// packed fp32x2 FMA: d.lo += a.lo*b.lo ; d.hi += a.hi*b.hi
__device__ __forceinline__ void ffma2(u64& d, u64 a, u64 b) {
    asm("fma.rn.f32x2 %0, %1, %2, %0;" : "+l"(d) : "l"(a), "l"(b));
}
__device__ __forceinline__ u64 dup2(float x) {
    u64 r; asm("mov.b64 %0, {%1, %1};" : "=l"(r) : "f"(x)); return r;
}
__device__ __forceinline__ float2 unpk(u64 v) {
    float2 f; asm("mov.b64 {%0, %1}, %2;" : "=f"(f.x), "=f"(f.y) : "l"(v)); return f;
}

// Scratch (device globals; zero-init at load; pad cols/rows never written -> stay 0)
__device__ float g_A[Ldim * HP];
__device__ float g_B[Ldim * HP];
__device__ float g_C[Ldim * HP];
__device__ float g_H1[Ldim * HP];
__device__ float g_H2[Ldim * HP];
__device__ float g_attn[Ldim];
__device__ float g_X[TP * HP];        // pooled+relu h1 rows for all windows
__device__ float g_W2p[HP * HP];      // padded sW2
__device__ float g_sW3p[HP];
__device__ float g_sb2p[HP];

// ---------------------------------------------------------------------------
// Skinny GEMM for precompute: out[32 rows][HP] = act(in[32xK] @ W[Kx150] (+b))
// f32x2 inner loop: 16 FFMA2 per k instead of 32 FFMA.
// ---------------------------------------------------------------------------
__device__ __forceinline__ void gemm_body(
    const float* __restrict__ in, int lda, int K,
    const float* __restrict__ W, const float* __restrict__ bias, int do_relu,
    float* __restrict__ out, int bm, float* sm)
{
    float* inT = sm;             // [16][32] transposed input tile
    float* Ws  = sm + 16 * 32;   // [16][160]

    const int tid = threadIdx.x;          // 160 threads
    const int ti  = tid / 40;
    const int ci  = tid % 40;
    const int r0  = ti * 8;
    const int c0  = ci * 4;
    const int row_base = bm * 32;

    u64 acc[4][4];
#pragma unroll
    for (int i = 0; i < 4; i++)
#pragma unroll
        for (int j = 0; j < 4; j++) acc[i][j] = 0ull;

    for (int k0 = 0; k0 < K; k0 += 16) {
        if (tid < 128) {
            int m = tid >> 2, q = tid & 3;
            float4 v = *(const float4*)(in + (size_t)(row_base + m) * lda + k0 + q * 4);
            inT[(q * 4 + 0) * 32 + m] = v.x;
            inT[(q * 4 + 1) * 32 + m] = v.y;
            inT[(q * 4 + 2) * 32 + m] = v.z;
            inT[(q * 4 + 3) * 32 + m] = v.w;
        }
#pragma unroll
        for (int t = 0; t < 16; t++) {
            int idx = tid + t * 160;
            int r = idx / 160, c = idx - r * 160;
            float v = 0.f;
            if (c < Hdim && (k0 + r) < K) v = W[(size_t)(k0 + r) * Hdim + c];
            Ws[idx] = v;
        }
        __syncthreads();

#pragma unroll
        for (int k = 0; k < 16; k++) {
            const u64* ap = (const u64*)(inT + k * 32 + r0);   // 4 row-pairs (LDS.64)
            u64 a0 = ap[0], a1 = ap[1], a2 = ap[2], a3 = ap[3];
            float4 b = *(const float4*)(Ws + k * 160 + c0);
            u64 b0 = dup2(b.x), b1 = dup2(b.y), b2 = dup2(b.z), b3 = dup2(b.w);
            ffma2(acc[0][0], a0, b0); ffma2(acc[0][1], a0, b1);
            ffma2(acc[0][2], a0, b2); ffma2(acc[0][3], a0, b3);
            ffma2(acc[1][0], a1, b0); ffma2(acc[1][1], a1, b1);
            ffma2(acc[1][2], a1, b2); ffma2(acc[1][3], a1, b3);
            ffma2(acc[2][0], a2, b0); ffma2(acc[2][1], a2, b1);
            ffma2(acc[2][2], a2, b2); ffma2(acc[2][3], a2, b3);
            ffma2(acc[3][0], a3, b0); ffma2(acc[3][1], a3, b1);
            ffma2(acc[3][2], a3, b2); ffma2(acc[3][3], a3, b3);
        }
        __syncthreads();
    }

#pragma unroll
    for (int i = 0; i < 4; i++) {
#pragma unroll
        for (int j = 0; j < 4; j++) {
            int c = c0 + j;
            if (c < Hdim) {
                float2 v = unpk(acc[i][j]);
                float vlo = v.x, vhi = v.y;
                if (bias) { vlo += bias[c]; vhi += bias[c]; }
                if (do_relu) { vlo = fmaxf(vlo, 0.f); vhi = fmaxf(vhi, 0.f); }
                int m = row_base + r0 + 2 * i;
                out[(size_t)m * HP + c]       = vlo;
                out[(size_t)(m + 1) * HP + c] = vhi;
            }
        }
    }
}

__global__ void gemm_pre_kernel(const float* __restrict__ states,
                                const float* __restrict__ embeds,
                                const float* __restrict__ aW1,
                                const float* __restrict__ ab1,
                                const float* __restrict__ sW1)
{
    extern __shared__ float sm[];
    switch (blockIdx.y) {
        case 0: gemm_body(states, Sdim, Sdim, sW1,                    nullptr, 0, g_A,  blockIdx.x, sm); break;
        case 1: gemm_body(states, Sdim, Sdim, sW1 + Sdim * Hdim,      nullptr, 0, g_B,  blockIdx.x, sm); break;
        case 2: gemm_body(states, Sdim, Sdim, aW1,                    ab1,     1, g_H1, blockIdx.x, sm); break;
        default: gemm_body(embeds, Edim, Edim, sW1 + 2 * Sdim * Hdim, nullptr, 0, g_C,  blockIdx.x, sm); break;
    }
}

__global__ void gemm_l2_kernel(const float* __restrict__ aW2,
                               const float* __restrict__ ab2)
{
    extern __shared__ float sm[];
    gemm_body(g_H1, HP, Hdim, aW2, ab2, 1, g_H2, blockIdx.x, sm);
}

__global__ void attn_l3_kernel(const float* __restrict__ aW3,
                               const float* __restrict__ ab3)
{
    int lane = threadIdx.x & 31;
    int m = blockIdx.x * 4 + (threadIdx.x >> 5);
    float acc = 0.f;
#pragma unroll
    for (int i = 0; i < 5; i++) {
        int c = lane + 32 * i;
        float w = (c < Hdim) ? aW3[c] : 0.f;
        acc += g_H2[(size_t)m * HP + c] * w;
    }
#pragma unroll
    for (int o = 16; o > 0; o >>= 1) acc += __shfl_xor_sync(0xffffffffu, acc, o);
    if (lane == 0) g_attn[m] = acc + ab3[0];
}

// Pad sW2 -> [160][160], sW3/sb2 -> [160]
__global__ void pad_kernel(const float* __restrict__ sW2,
                           const float* __restrict__ sW3,
                           const float* __restrict__ sb2)
{
    int idx = blockIdx.x * 256 + threadIdx.x;
    if (idx < HP * HP) {
        int r = idx / HP, c = idx - r * HP;
        g_W2p[idx] = (r < Hdim && c < Hdim) ? sW2[r * Hdim + c] : 0.f;
    }
    if (idx < HP) {
        g_sW3p[idx] = (idx < Hdim) ? sW3[idx] : 0.f;
        g_sb2p[idx] = (idx < Hdim) ? sb2[idx] : 0.f;
    }
}

// ---------------------------------------------------------------------------
// Pool kernel: X[t] = relu(A[s] + B[s+n-1] + softmax(attn win).C + sb1)
// ---------------------------------------------------------------------------
__global__ void pool_kernel(const float* __restrict__ sb1)
{
    __shared__ float attw[140];
    __shared__ float wsm[128 * 12];

    const int tid = threadIdx.x;
    const int n   = blockIdx.y + 1;
    const int s0  = blockIdx.x * 128;
    const int M   = Ldim - n + 1;
    const int nw  = 128 + n - 1;
    const int off = (n - 1) * (Ldim + 1) - (n * (n - 1)) / 2;

    for (int idx = tid; idx < nw; idx += 256) {
        int g = s0 + idx;
        attw[idx] = (g < Ldim) ? g_attn[g] : 0.f;
    }
    __syncthreads();

    if (tid < 128) {
        int r = tid;
        float mx = -1e30f;
        for (int j = 0; j < n; j++) mx = fmaxf(mx, attw[r + j]);
        float s = 0.f;
        for (int j = 0; j < n; j++) {
            float e = expf(attw[r + j] - mx);
            wsm[r * 12 + j] = e;
            s += e;
        }
        float inv = 1.f / s;
        for (int j = 0; j < n; j++) wsm[r * 12 + j] *= inv;
    }
    __syncthreads();

    const int warp = tid >> 5, lane = tid & 31;
    for (int r = warp; r < 128; r += 8) {
        int start = s0 + r;
        if (start >= M) continue;
        float wj[MAXN];
        for (int j = 0; j < n; j++) wj[j] = wsm[r * 12 + j];
        size_t tb = (size_t)(off + start) * HP;
        size_t ab = (size_t)start * HP;
        size_t bb = (size_t)(start + n - 1) * HP;
#pragma unroll
        for (int k = 0; k < 5; k++) {
            int c = lane + 32 * k;
            float v = 0.f;
            if (c < Hdim) {
                v = g_A[ab + c] + g_B[bb + c] + sb1[c];
                for (int j = 0; j < n; j++)
                    v += wj[j] * g_C[(size_t)(start + j) * HP + c];
                v = fmaxf(v, 0.f);
            }
            g_X[tb + c] = v;
        }
    }
}

// ---------------------------------------------------------------------------
// Big GEMM + fused layer3: out[t] = sW3 . relu(X[t] @ W2 + sb2) + sb3
// BM=64, BN=160, BK=16, 320 threads, f32x2 inner loop.
// ---------------------------------------------------------------------------
#define G2T 320
#define ITS 68    // multiple of 4 (alignment), 68 % 32 = 4 banks offset

__global__ void gemm2_kernel(const float* __restrict__ sb3,
                             float* __restrict__ out)
{
    __shared__ float inT[16 * ITS];
    __shared__ float Ws[16 * 160];
    __shared__ float red[64 * 41];
    __shared__ float sW3s[HP];
    __shared__ float sb2s[HP];

    const int tid = threadIdx.x;
    const int ti  = tid / 40;            // 0..7 (8 rows each)
    const int ci  = tid % 40;            // 0..39 (4 cols each)
    const int r0  = ti * 8;
    const int c0  = ci * 4;
    const size_t t0 = (size_t)blockIdx.x * 64;

    if (tid < HP) { sW3s[tid] = g_sW3p[tid]; sb2s[tid] = g_sb2p[tid]; }

    u64 acc[4][4];
#pragma unroll
    for (int i = 0; i < 4; i++)
#pragma unroll
        for (int j = 0; j < 4; j++) acc[i][j] = 0ull;

    for (int k0 = 0; k0 < HP; k0 += 16) {
        if (tid < 256) {
            int m = tid >> 2, q = tid & 3;
            float4 v = *(const float4*)(g_X + (t0 + m) * HP + k0 + q * 4);
            inT[(q * 4 + 0) * ITS + m] = v.x;
            inT[(q * 4 + 1) * ITS + m] = v.y;
            inT[(q * 4 + 2) * ITS + m] = v.z;
            inT[(q * 4 + 3) * ITS + m] = v.w;
        }
#pragma unroll
        for (int it = 0; it < 2; it++) {
            int idx = tid + it * G2T;    // 0..639 float4 slots
            int k = idx / 40, q = idx - k * 40;
            *(float4*)(Ws + k * 160 + q * 4) =
                *(const float4*)(g_W2p + (k0 + k) * HP + q * 4);
        }
        __syncthreads();

#pragma unroll
        for (int k = 0; k < 16; k++) {
            const u64* ap = (const u64*)(inT + k * ITS + r0);
            u64 a0 = ap[0], a1 = ap[1], a2 = ap[2], a3 = ap[3];
            float4 b = *(const float4*)(Ws + k * 160 + c0);
            u64 b0 = dup2(b.x), b1 = dup2(b.y), b2 = dup2(b.z), b3 = dup2(b.w);
            ffma2(acc[0][0], a0, b0); ffma2(acc[0][1], a0, b1);
            ffma2(acc[0][2], a0, b2); ffma2(acc[0][3], a0, b3);
            ffma2(acc[1][0], a1, b0); ffma2(acc[1][1], a1, b1);
            ffma2(acc[1][2], a1, b2); ffma2(acc[1][3], a1, b3);
            ffma2(acc[2][0], a2, b0); ffma2(acc[2][1], a2, b1);
            ffma2(acc[2][2], a2, b2); ffma2(acc[2][3], a2, b3);
            ffma2(acc[3][0], a3, b0); ffma2(acc[3][1], a3, b1);
            ffma2(acc[3][2], a3, b2); ffma2(acc[3][3], a3, b3);
        }
        __syncthreads();
    }

    // epilogue: bias + relu + dot with sW3, partial per col-group
#pragma unroll
    for (int i = 0; i < 4; i++) {
        float plo = 0.f, phi = 0.f;
#pragma unroll
        for (int j = 0; j < 4; j++) {
            int c = c0 + j;
            float2 v = unpk(acc[i][j]);
            plo += sW3s[c] * fmaxf(v.x + sb2s[c], 0.f);
            phi += sW3s[c] * fmaxf(v.y + sb2s[c], 0.f);
        }
        red[(r0 + 2 * i) * 41 + ci]     = plo;
        red[(r0 + 2 * i + 1) * 41 + ci] = phi;
    }
    __syncthreads();

    if (tid < 64) {
        float s = sb3[0];
#pragma unroll
        for (int cc = 0; cc < 40; cc++) s += red[tid * 41 + cc];
        size_t t = t0 + tid;
        if (t < Ttot) out[t] = s;
    }
}

// ---------------------------------------------------------------------------
extern "C" void kernel_launch(void* const* d_in, const int* in_sizes, int n_in,
                              void* d_out, int out_size)
{
    const float* embeds = (const float*)d_in[0];
    const float* states = (const float*)d_in[1];
    const float* aW1    = (const float*)d_in[2];
    const float* ab1    = (const float*)d_in[3];
    const float* aW2    = (const float*)d_in[4];
    const float* ab2    = (const float*)d_in[5];
    const float* aW3    = (const float*)d_in[6];
    const float* ab3    = (const float*)d_in[7];
    const float* sW1    = (const float*)d_in[8];
    const float* sb1    = (const float*)d_in[9];
    const float* sW2    = (const float*)d_in[10];
    const float* sb2    = (const float*)d_in[11];
    const float* sW3    = (const float*)d_in[12];
    const float* sb3    = (const float*)d_in[13];
    float* out = (float*)d_out;

    const int gemm_smem = (16 * 32 + 16 * 160) * 4;

    pad_kernel<<<(HP * HP + 255) / 256, 256>>>(sW2, sW3, sb2);
    gemm_pre_kernel<<<dim3(128, 4), 160, gemm_smem>>>(states, embeds, aW1, ab1, sW1);
    gemm_l2_kernel<<<dim3(128, 1), 160, gemm_smem>>>(aW2, ab2);
    attn_l3_kernel<<<1024, 128>>>(aW3, ab3);
    pool_kernel<<<dim3(32, 10), 256>>>(sb1);
    gemm2_kernel<<<TP / 64, G2T>>>(sb3, out);
}